// round 15
// baseline (speedup 1.0000x reference)
#include <cuda_runtime.h>
#include <cuda_fp16.h>
#include <cstdint>
#include <math_constants.h>

typedef unsigned long long ull;
typedef unsigned int u32;

#define L_TOT 32768
#define D_DIM 64
#define NEMB  16384
#define TL 128
#define TN 256
#define NQ 8                          /* codebook eighths */
#define NT_ITEM (NEMB/TN/NQ)          /* 8 e-tiles per item */
#define N_ITEMS ((L_TOT/TL)*NQ)       /* 2048 work items */
#define NBLOCKS 444                   /* 148 SMs x 3 CTAs, persistent */
#define LD_TOT (L_TOT*D_DIM)
#define CAP 24

// dynamic smem (bytes)
#define ES0_OFF 0                     // fp16 e tile buf0 (32 KB)
#define ES1_OFF 32768                 // buf1; also z fp16 staging in item prolog
#define MS_OFF  65536                 // float M_s[128]
#define ZZS_OFF 66048                 // float ZZ_s[128]
#define WRK_OFF 66560                 // int current work item
#define SMEM_TOTAL 66688

__device__ double g_loss;
__device__ unsigned g_done;
__device__ unsigned g_work;
__device__ ull g_red[L_TOT];          // per-row (d_bits<<32)|n merge keys
__device__ float g_zz[L_TOT];
__device__ float g_marg[L_TOT];
__device__ uint4 g_zh[L_TOT*8];       // z rows fp16
__device__ uint4 g_eh[NEMB*8];        // e rows * 2^14 fp16

// init key: d = +inf so any finite rescored key wins; seeds give thr = inf
#define RED_INIT ((((ull)0x7F800000u) << 32) | 0xFFFFFFFFull)

// ---- prep: zz, margin, fp16 conversions; resets counters + merge keys ----
__global__ void vq_prep(const float* __restrict__ z, const float* __restrict__ emb) {
    int bid = blockIdx.x, tid = threadIdx.x;
    if (bid == 0 && tid == 0) { g_loss = 0.0; g_done = 0u; g_work = 0u; }
    int gidx = bid * 256 + tid;
    if (gidx < L_TOT) g_red[gidx] = RED_INIT;
    bool is_z = bid < 128;
    int row = is_z ? bid * 256 + tid : (bid - 128) * 256 + tid;
    const float4* src = (const float4*)((is_z ? z : emb) + (size_t)row * D_DIM);
    float4 v[16];
    #pragma unroll
    for (int q = 0; q < 16; q++) v[q] = src[q];
    float scale = is_z ? 1.0f : 16384.0f;
    if (is_z) {
        float a = 0.f, l1 = 0.f;
        #pragma unroll
        for (int q = 0; q < 16; q++) {
            a = __fmaf_rn(v[q].x, v[q].x, a); a = __fmaf_rn(v[q].y, v[q].y, a);
            a = __fmaf_rn(v[q].z, v[q].z, a); a = __fmaf_rn(v[q].w, v[q].w, a);
            l1 += fabsf(v[q].x) + fabsf(v[q].y) + fabsf(v[q].z) + fabsf(v[q].w);
        }
        g_zz[row] = a;
        g_marg[row] = __fmaf_rn(l1, 2.5e-7f, 4e-5f);
    }
    uint4* dst = (is_z ? g_zh : g_eh) + row * 8;
    const float* f = (const float*)v;
    #pragma unroll
    for (int q = 0; q < 8; q++) {
        u32 h[4];
        #pragma unroll
        for (int p = 0; p < 4; p++) {
            __half h0 = __float2half_rn(f[q * 8 + 2 * p] * scale);
            __half h1 = __float2half_rn(f[q * 8 + 2 * p + 1] * scale);
            h[p] = (u32)__half_as_ushort(h0) | ((u32)__half_as_ushort(h1) << 16);
        }
        uint4 u; u.x = h[0]; u.y = h[1]; u.z = h[2]; u.w = h[3];
        dst[q] = u;
    }
}

// ---- portable PTX helpers ----
__device__ __forceinline__ void cp16(u32 saddr, const void* g) {
    asm volatile("cp.async.cg.shared.global [%0], [%1], 16;" :: "r"(saddr), "l"(g));
}
__device__ __forceinline__ void ldsm4(u32& r0, u32& r1, u32& r2, u32& r3, u32 addr) {
    asm volatile("ldmatrix.sync.aligned.m8n8.x4.shared.b16 {%0,%1,%2,%3}, [%4];"
                 : "=r"(r0), "=r"(r1), "=r"(r2), "=r"(r3) : "r"(addr));
}
__device__ __forceinline__ void mma16816(float* c, const u32* a, const u32* b) {
    asm volatile("mma.sync.aligned.m16n8k16.row.col.f32.f16.f16.f32 "
                 "{%0,%1,%2,%3},{%4,%5,%6,%7},{%8,%9},{%0,%1,%2,%3};"
                 : "+f"(c[0]), "+f"(c[1]), "+f"(c[2]), "+f"(c[3])
                 : "r"(a[0]), "r"(a[1]), "r"(a[2]), "r"(a[3]), "r"(b[0]), "r"(b[1]));
}

// exact fp32 rescore (R2-validated chain); z row from gmem (L2-resident)
__device__ __forceinline__ void rescore(const float* __restrict__ emb,
                                        const float* __restrict__ zrow,
                                        float zz, u32 n, ull& best) {
    const float4* e4 = (const float4*)(emb + (size_t)n * D_DIM);
    const float4* z4 = (const float4*)zrow;
    float dot = 0.f;
    #pragma unroll
    for (int q = 0; q < 16; q++) {
        float4 e = e4[q], zv = z4[q];
        dot = __fmaf_rn(e.x, zv.x, dot); dot = __fmaf_rn(e.y, zv.y, dot);
        dot = __fmaf_rn(e.z, zv.z, dot); dot = __fmaf_rn(e.w, zv.w, dot);
    }
    float d = __fmaf_rn(-2.f, dot, zz);
    ull key = ((ull)__float_as_uint(d) << 32) | n;
    if (key < best) best = key;
}

__global__ void __launch_bounds__(256, 3) vq_main(
    const float* __restrict__ z, const float* __restrict__ emb)
{
    extern __shared__ char smem[];
    u32 sb = (u32)__cvta_generic_to_shared(smem);
    float* MS  = (float*)(smem + MS_OFF);
    float* ZZS = (float*)(smem + ZZS_OFF);
    volatile int* WRK = (volatile int*)(smem + WRK_OFF);
    const int tid  = threadIdx.x;
    const int lane = tid & 31;
    const int wid  = tid >> 5;
    const int mg   = wid >> 1;        // m-group: rows mg*32..+31
    const int nh   = wid & 1;         // n-half of tile
    const int rbase = mg * 32 + (lane >> 2);   // first of this thread's 4 rows
    // per-lane B ldmatrix base (C2 = C1 ^ 64 — swizzle XOR identity)
    const u32 C1 = (u32)((lane & 7) * 128 + ((((lane >> 3)) ^ (lane & 7)) << 4));

    // ---- persistent work loop ----
    for (;;) {
        if (tid == 0) *WRK = (int)atomicAdd(&g_work, 1u);
        __syncthreads();                        // also isolates prior item's smem reads
        int w = *WRK;
        if (w >= N_ITEMS) break;
        const int l0  = (w >> 3) * TL;
        const int ns0 = (w & 7) * (NEMB / NQ);

        // ---- item prolog: z fp16 -> ES1, M/zz -> smem, e tile 0 -> ES0 ----
        #pragma unroll
        for (int j = 0; j < 4; j++) {
            int v = tid + 256 * j;              // 128 rows x 8 chunks
            int row = v >> 3, c = v & 7;
            cp16(sb + ES1_OFF + row * 128 + ((c ^ (row & 7)) << 4),
                 &g_zh[(size_t)(l0 + row) * 8 + c]);
        }
        #pragma unroll
        for (int j = 0; j < 8; j++) {
            int v = tid + 256 * j;              // 256 rows x 8 chunks
            int row = v >> 3, c = v & 7;
            cp16(sb + ES0_OFF + row * 128 + ((c ^ (row & 7)) << 4),
                 &g_eh[(size_t)(ns0 + row) * 8 + c]);
        }
        asm volatile("cp.async.commit_group;");
        if (tid < TL) { MS[tid] = g_marg[l0 + tid]; ZZS[tid] = g_zz[l0 + tid]; }
        asm volatile("cp.async.wait_group 0;");
        __syncthreads();

        // ---- extract A fragments (2 m-tiles x 4 k-steps x 4 regs) ----
        u32 A[2][4][4];
        #pragma unroll
        for (int mt = 0; mt < 2; mt++)
            #pragma unroll
            for (int s = 0; s < 4; s++) {
                int row = mg * 32 + mt * 16 + (lane & 15);
                int chunk = 2 * s + (lane >> 4);
                ldsm4(A[mt][s][0], A[mt][s][1], A[mt][s][2], A[mt][s][3],
                      sb + ES1_OFF + row * 128 + ((chunk ^ (row & 7)) << 4));
            }

        // ---- seed thresholds from global best-so-far (certified: thr >= dhat(n*) ) ----
        float thr[4], At[4];
        int cnt[4];
        u32 cand[4][CAP];
        #pragma unroll
        for (int p = 0; p < 4; p++) {
            int rr = rbase + 8 * p;
            float dprev = __uint_as_float((u32)(g_red[l0 + rr] >> 32));
            thr[p] = dprev + MS[rr];            // inf stays inf
            At[p] = __fmaf_rn(ZZS[rr] - thr[p], 8192.f, -2.f);
            cnt[p] = 0;
        }
        __syncthreads();                        // A extracted: ES1 reusable

        #pragma unroll 1
        for (int t = 0; t < NT_ITEM; t++) {
            if (t + 1 < NT_ITEM) {
                u32 dbase = sb + (((t + 1) & 1) ? ES1_OFF : ES0_OFF);
                #pragma unroll
                for (int j = 0; j < 8; j++) {
                    int v = tid + 256 * j;
                    int row = v >> 3, c = v & 7;
                    cp16(dbase + row * 128 + ((c ^ (row & 7)) << 4),
                         &g_eh[(size_t)(ns0 + (t + 1) * TN + row) * 8 + c]);
                }
                asm volatile("cp.async.commit_group;");
                asm volatile("cp.async.wait_group 1;");
            } else {
                asm volatile("cp.async.wait_group 0;");
            }
            __syncthreads();

            u32 bufb = sb + ((t & 1) ? ES1_OFF : ES0_OFF) + nh * 16384;

            #pragma unroll 2
            for (int i = 0; i < 16; i++) {
                u32 ab = bufb + (u32)i * 1024;
                u32 b[8];
                ldsm4(b[0], b[1], b[2], b[3], ab + C1);
                ldsm4(b[4], b[5], b[6], b[7], ab + (C1 ^ 64u));
                // 4 independent accumulation chains of depth 2
                float aA[8], aB[8];
                #pragma unroll
                for (int q = 0; q < 8; q++) { aA[q] = 0.f; aB[q] = 0.f; }
                mma16816(aA,     A[0][0], b + 0);
                mma16816(aA + 4, A[1][0], b + 0);
                mma16816(aB,     A[0][2], b + 4);
                mma16816(aB + 4, A[1][2], b + 4);
                mma16816(aA,     A[0][1], b + 2);
                mma16816(aA + 4, A[1][1], b + 2);
                mma16816(aB,     A[0][3], b + 6);
                mma16816(aB + 4, A[1][3], b + 6);

                u32 nb = (u32)(ns0 + t * TN + nh * 128 + i * 8 + 2 * (lane & 3));
                #pragma unroll
                for (int p = 0; p < 4; p++) {
                    float s0 = aA[2 * p] + aB[2 * p];
                    float s1 = aA[2 * p + 1] + aB[2 * p + 1];
                    if (__builtin_expect(fmaxf(s0, s1) > At[p], 0)) {
                        int rr = rbase + 8 * p;
                        float zzp = ZZS[rr], Mp = MS[rr];
                        #pragma unroll
                        for (int h = 0; h < 2; h++) {
                            float d = __fmaf_rn(h ? s1 : s0, -0x1p-13f, zzp);
                            if (d < thr[p]) {
                                if (cnt[p] < CAP) cand[p][cnt[p]] = nb + h;
                                cnt[p]++;
                                thr[p] = fminf(thr[p], d + Mp);
                            }
                        }
                        At[p] = __fmaf_rn(zzp - thr[p], 8192.f, -2.f);
                    }
                }
            }

            // quad-share thr (already includes +M) to tighten thresholds
            #pragma unroll
            for (int p = 0; p < 4; p++) {
                float tq = thr[p];
                tq = fminf(tq, __shfl_xor_sync(0xFFFFFFFFu, tq, 1));
                tq = fminf(tq, __shfl_xor_sync(0xFFFFFFFFu, tq, 2));
                thr[p] = tq;
                At[p] = __fmaf_rn(ZZS[rbase + 8 * p] - tq, 8192.f, -2.f);
            }
            __syncthreads();
        }

        // ---- deferred exact rescoring; merge via global per-row atomicMin ----
        #pragma unroll
        for (int p = 0; p < 4; p++) {
            int rr = rbase + 8 * p;
            ull best = ~0ull;
            const float* zrow = z + (size_t)(l0 + rr) * D_DIM;
            float zzp = ZZS[rr];
            if (__builtin_expect(cnt[p] <= CAP, 1)) {
                for (int i = 0; i < cnt[p]; i++)
                    rescore(emb, zrow, zzp, cand[p][i], best);
            } else {
                for (u32 n = (u32)ns0; n < (u32)(ns0 + NEMB / NQ); n++)
                    rescore(emb, zrow, zzp, n, best);
            }
            if (best != ~0ull) atomicMin(&g_red[l0 + rr], best);
        }
    }
}

// ---- post: indices, z_q_st, loss, loss scalar (fused finish) ----
__global__ void __launch_bounds__(128) vq_post(
    const float* __restrict__ z, const float* __restrict__ emb,
    float* __restrict__ out, int out_size)
{
    int row = blockIdx.x * 128 + threadIdx.x;
    int idx = (int)(u32)(g_red[row] & 0xFFFFFFFFull);
    int ipos = LD_TOT + 1 + row;
    if (ipos < out_size) out[ipos] = (float)idx;

    const float4* eq = (const float4*)(emb + (size_t)idx * D_DIM);
    const float4* zg = (const float4*)(z + (size_t)row * D_DIM);
    int obase = row * D_DIM;
    bool wr = (obase + D_DIM) <= out_size;
    float4* og = (float4*)(out + obase);
    double ls = 0.0;
    #pragma unroll
    for (int q = 0; q < 16; q++) {
        float4 e4 = eq[q], z4 = zg[q];
        float t0 = e4.x - z4.x, t1 = e4.y - z4.y, t2 = e4.z - z4.z, t3 = e4.w - z4.w;
        if (wr) {
            float4 o; o.x = z4.x + t0; o.y = z4.y + t1; o.z = z4.z + t2; o.w = z4.w + t3;
            og[q] = o;
        }
        ls += (double)t0 * t0 + (double)t1 * t1 + (double)t2 * t2 + (double)t3 * t3;
    }
    #pragma unroll
    for (int off = 16; off > 0; off >>= 1) ls += __shfl_down_sync(0xFFFFFFFFu, ls, off);
    if ((threadIdx.x & 31) == 0) atomicAdd(&g_loss, ls);

    __syncthreads();
    if (threadIdx.x == 0) {
        __threadfence();
        unsigned old = atomicAdd(&g_done, 1u);
        if (old == gridDim.x - 1) {
            double total = atomicAdd(&g_loss, 0.0);
            double mmean = total / (double)LD_TOT;
            if (LD_TOT < out_size) out[LD_TOT] = (float)(1.25 * mmean);
            g_done = 0u;                       // reset for next graph replay
        }
    }
}

extern "C" void kernel_launch(void* const* d_in, const int* in_sizes, int n_in,
                              void* d_out, int out_size)
{
    const float* zp = (const float*)d_in[0];
    const float* ep = (const float*)d_in[1];
    if (n_in >= 2 && in_sizes[0] == NEMB * D_DIM && in_sizes[1] == L_TOT * D_DIM) {
        const float* tmp = zp; zp = ep; ep = tmp;
    }
    float* out = (float*)d_out;

    cudaFuncSetAttribute(vq_main, cudaFuncAttributeMaxDynamicSharedMemorySize, SMEM_TOTAL);

    vq_prep<<<192, 256>>>(zp, ep);
    vq_main<<<NBLOCKS, 256, SMEM_TOTAL>>>(zp, ep);
    vq_post<<<L_TOT / 128, 128>>>(zp, ep, out, out_size);
}

// round 16
// speedup vs baseline: 2.8627x; 2.8627x over previous
#include <cuda_runtime.h>
#include <cuda_fp16.h>
#include <cstdint>
#include <math_constants.h>

typedef unsigned long long ull;
typedef unsigned int u32;

#define L_TOT 32768
#define D_DIM 64
#define NEMB  16384
#define TL 128
#define TN 256
#define NT (NEMB/TN)
#define LD_TOT (L_TOT*D_DIM)
#define CAP 20

// dynamic smem (bytes)
#define ES0_OFF 0                     // fp16 e tile buf0 (32 KB)
#define ES1_OFF 32768                 // buf1; also staging for z fp16 in prolog
#define ZS_OFF  65536                 // fp32 z tile: 128 x 256B (32 KB)
#define RED_OFF 98304                 // ull red[128][8] (8 KB)
#define IDX_OFF 106496                // int idx[128]
#define SMEM_TOTAL 107008

__device__ double g_loss;
__device__ unsigned g_done;
__device__ float g_zz[L_TOT];
__device__ float g_marg[L_TOT];
__device__ uint4 g_zh[L_TOT*8];       // z rows fp16
__device__ uint4 g_eh[NEMB*8];        // e rows * 2^14 fp16

// ---- prep: zz, margin, fp16 conversions; resets accumulators ----
__global__ void vq_prep(const float* __restrict__ z, const float* __restrict__ emb) {
    int bid = blockIdx.x, tid = threadIdx.x;
    if (bid == 0 && tid == 0) { g_loss = 0.0; g_done = 0u; }
    bool is_z = bid < 128;
    int row = is_z ? bid * 256 + tid : (bid - 128) * 256 + tid;
    const float4* src = (const float4*)((is_z ? z : emb) + (size_t)row * D_DIM);
    float4 v[16];
    #pragma unroll
    for (int q = 0; q < 16; q++) v[q] = src[q];
    float scale = is_z ? 1.0f : 16384.0f;
    if (is_z) {
        float a = 0.f, l1 = 0.f;
        #pragma unroll
        for (int q = 0; q < 16; q++) {
            a = __fmaf_rn(v[q].x, v[q].x, a); a = __fmaf_rn(v[q].y, v[q].y, a);
            a = __fmaf_rn(v[q].z, v[q].z, a); a = __fmaf_rn(v[q].w, v[q].w, a);
            l1 += fabsf(v[q].x) + fabsf(v[q].y) + fabsf(v[q].z) + fabsf(v[q].w);
        }
        g_zz[row] = a;
        g_marg[row] = __fmaf_rn(l1, 2.5e-7f, 4e-5f);
    }
    uint4* dst = (is_z ? g_zh : g_eh) + row * 8;
    const float* f = (const float*)v;
    #pragma unroll
    for (int q = 0; q < 8; q++) {
        u32 h[4];
        #pragma unroll
        for (int p = 0; p < 4; p++) {
            __half h0 = __float2half_rn(f[q * 8 + 2 * p] * scale);
            __half h1 = __float2half_rn(f[q * 8 + 2 * p + 1] * scale);
            h[p] = (u32)__half_as_ushort(h0) | ((u32)__half_as_ushort(h1) << 16);
        }
        uint4 u; u.x = h[0]; u.y = h[1]; u.z = h[2]; u.w = h[3];
        dst[q] = u;
    }
}

// ---- portable PTX helpers ----
__device__ __forceinline__ void cp16(u32 saddr, const void* g) {
    asm volatile("cp.async.cg.shared.global [%0], [%1], 16;" :: "r"(saddr), "l"(g));
}
__device__ __forceinline__ void ldsm4(u32& r0, u32& r1, u32& r2, u32& r3, u32 addr) {
    asm volatile("ldmatrix.sync.aligned.m8n8.x4.shared.b16 {%0,%1,%2,%3}, [%4];"
                 : "=r"(r0), "=r"(r1), "=r"(r2), "=r"(r3) : "r"(addr));
}
__device__ __forceinline__ void mma16816(float* c, const u32* a, const u32* b) {
    asm volatile("mma.sync.aligned.m16n8k16.row.col.f32.f16.f16.f32 "
                 "{%0,%1,%2,%3},{%4,%5,%6,%7},{%8,%9},{%0,%1,%2,%3};"
                 : "+f"(c[0]), "+f"(c[1]), "+f"(c[2]), "+f"(c[3])
                 : "r"(a[0]), "r"(a[1]), "r"(a[2]), "r"(a[3]), "r"(b[0]), "r"(b[1]));
}

// exact fp32 rescore (R2-validated chain) — called only AFTER the mainloop
__device__ __forceinline__ void rescore(const float* __restrict__ emb, const float* zsp,
                                        float zz, u32 n, ull& best) {
    const float4* e4 = (const float4*)(emb + (size_t)n * D_DIM);
    const float4* z4 = (const float4*)zsp;
    float dot = 0.f;
    #pragma unroll
    for (int q = 0; q < 16; q++) {
        float4 e = e4[q], zv = z4[q];
        dot = __fmaf_rn(e.x, zv.x, dot); dot = __fmaf_rn(e.y, zv.y, dot);
        dot = __fmaf_rn(e.z, zv.z, dot); dot = __fmaf_rn(e.w, zv.w, dot);
    }
    float d = __fmaf_rn(-2.f, dot, zz);
    ull key = ((ull)__float_as_uint(d) << 32) | n;
    if (key < best) best = key;
}

__global__ void __launch_bounds__(256, 2) vq_main(
    const float* __restrict__ z, const float* __restrict__ emb,
    float* __restrict__ out, int out_size)
{
    extern __shared__ char smem[];
    u32 sb = (u32)__cvta_generic_to_shared(smem);
    const int tid  = threadIdx.x;
    const int lane = tid & 31;
    const int wid  = tid >> 5;
    const int mg   = wid >> 1;        // m-group: rows mg*32..+31
    const int nh   = wid & 1;         // n-half of tile
    const int l0   = blockIdx.x * TL;
    ull* red = (ull*)(smem + RED_OFF);
    int* idx_s = (int*)(smem + IDX_OFF);

    // ---- prolog: stage z fp16 (ES1), z fp32 (ZS), e tile 0 (ES0) ----
    #pragma unroll
    for (int j = 0; j < 4; j++) {
        int v = tid + 256 * j;                     // 128 rows x 8 chunks fp16
        int row = v >> 3, c = v & 7;
        cp16(sb + ES1_OFF + row * 128 + ((c ^ (row & 7)) << 4),
             &g_zh[(size_t)(l0 + row) * 8 + c]);
    }
    {
        const float4* zg = (const float4*)(z + (size_t)l0 * D_DIM);
        #pragma unroll
        for (int j = 0; j < 8; j++) {
            int v = tid + 256 * j;
            cp16(sb + ZS_OFF + v * 16, zg + v);
        }
    }
    #pragma unroll
    for (int j = 0; j < 8; j++) {
        int v = tid + 256 * j;                     // e tile 0: 256 rows x 8 chunks
        int row = v >> 3, c = v & 7;
        cp16(sb + ES0_OFF + row * 128 + ((c ^ (row & 7)) << 4), &g_eh[(size_t)row * 8 + c]);
    }
    asm volatile("cp.async.commit_group;");
    asm volatile("cp.async.wait_group 0;");
    __syncthreads();

    // ---- extract A fragments (2 m-tiles x 4 k-steps x 4 regs) ----
    u32 A[2][4][4];
    #pragma unroll
    for (int mt = 0; mt < 2; mt++)
        #pragma unroll
        for (int s = 0; s < 4; s++) {
            int row = mg * 32 + mt * 16 + (lane & 15);
            int chunk = 2 * s + (lane >> 4);
            ldsm4(A[mt][s][0], A[mt][s][1], A[mt][s][2], A[mt][s][3],
                  sb + ES1_OFF + row * 128 + ((chunk ^ (row & 7)) << 4));
        }

    // per-row screening state (rows: mg*32 + lq + 8p); thr-only
    const int lq = lane >> 2;
    float zz[4], M[4], thr[4], At[4];
    int cnt[4];
    u32 cand[4][CAP];                 // local mem; written rarely, read once at end
    #pragma unroll
    for (int p = 0; p < 4; p++) {
        int rr = mg * 32 + lq + 8 * p;
        zz[p] = g_zz[l0 + rr]; M[p] = g_marg[l0 + rr];
        thr[p] = CUDART_INF_F; At[p] = -CUDART_INF_F;
        cnt[p] = 0;
    }
    __syncthreads();   // A frags extracted: ES1 reusable

    // per-lane B ldmatrix address constant (C2 = C1 ^ 64 swizzle identity)
    const u32 C1 = (u32)((lane & 7) * 128 + ((((lane >> 3)) ^ (lane & 7)) << 4));

    // software-pipeline state: double acc + double b + pending-n
    float acc0[8], acc1[8];
    u32 bX[8], bY[8];
    #pragma unroll
    for (int q = 0; q < 8; q++) { acc0[q] = 0.f; acc1[q] = -CUDART_INF_F; }
    u32 pnb = 0;

    #pragma unroll 1
    for (int t = 0; t < NT; t++) {
        if (t + 1 < NT) {
            u32 dbase = sb + (((t + 1) & 1) ? ES1_OFF : ES0_OFF);
            #pragma unroll
            for (int j = 0; j < 8; j++) {
                int v = tid + 256 * j;
                int row = v >> 3, c = v & 7;
                cp16(dbase + row * 128 + ((c ^ (row & 7)) << 4),
                     &g_eh[((size_t)(t + 1) * TN + row) * 8 + c]);
            }
            asm volatile("cp.async.commit_group;");
            asm volatile("cp.async.wait_group 1;");
        } else {
            asm volatile("cp.async.wait_group 0;");
        }
        __syncthreads();

        u32 bufb = sb + ((t & 1) ? ES1_OFF : ES0_OFF) + nh * 16384;
        u32 nbT  = (u32)(t * TN + nh * 128 + 2 * (lane & 3));

        // preload B for i=0
        ldsm4(bX[0], bX[1], bX[2], bX[3], bufb + C1);
        ldsm4(bX[4], bX[5], bX[6], bX[7], bufb + (C1 ^ 64u));

        #pragma unroll 4
        for (int i = 0; i < 16; i++) {
            u32*   bc  = (i & 1) ? bY : bX;
            u32*   bn  = (i & 1) ? bX : bY;
            float* cur = (i & 1) ? acc1 : acc0;
            float* prv = (i & 1) ? acc0 : acc1;

            // 8 MMAs for iter i (2 independent chains of depth 4)
            mma16816(cur,     A[0][0], bc + 0);
            mma16816(cur + 4, A[1][0], bc + 0);
            mma16816(cur,     A[0][1], bc + 2);
            mma16816(cur + 4, A[1][1], bc + 2);
            mma16816(cur,     A[0][2], bc + 4);
            mma16816(cur + 4, A[1][2], bc + 4);
            mma16816(cur,     A[0][3], bc + 6);
            mma16816(cur + 4, A[1][3], bc + 6);

            // prefetch B for iter i+1 (full iteration of slack before use)
            if (i < 15) {
                u32 ab = bufb + (u32)(i + 1) * 1024;
                ldsm4(bn[0], bn[1], bn[2], bn[3], ab + C1);
                ldsm4(bn[4], bn[5], bn[6], bn[7], ab + (C1 ^ 64u));
            }

            // deferred screen of iter i-1 (acc long complete; single branch)
            {
                bool hit = (fmaxf(prv[0], prv[1]) > At[0])
                         | (fmaxf(prv[2], prv[3]) > At[1])
                         | (fmaxf(prv[4], prv[5]) > At[2])
                         | (fmaxf(prv[6], prv[7]) > At[3]);
                if (__builtin_expect(hit, 0)) {
                    #pragma unroll
                    for (int p = 0; p < 4; p++) {
                        #pragma unroll
                        for (int h = 0; h < 2; h++) {
                            float d = __fmaf_rn(prv[2 * p + h], -0x1p-13f, zz[p]);
                            if (d < thr[p]) {
                                if (cnt[p] < CAP) cand[p][cnt[p]] = pnb + h;
                                cnt[p]++;
                                thr[p] = fminf(thr[p], d + M[p]);
                            }
                        }
                        At[p] = __fmaf_rn(zz[p] - thr[p], 8192.f, -2.f);
                    }
                }
            }
            #pragma unroll
            for (int q = 0; q < 8; q++) prv[q] = 0.f;   // ready for reuse as cur
            pnb = nbT + (u32)i * 8;
        }

        // quad-share thr (already includes +M) to tighten thresholds
        #pragma unroll
        for (int p = 0; p < 4; p++) {
            float tq = thr[p];
            tq = fminf(tq, __shfl_xor_sync(0xFFFFFFFFu, tq, 1));
            tq = fminf(tq, __shfl_xor_sync(0xFFFFFFFFu, tq, 2));
            thr[p] = tq;
            At[p] = __fmaf_rn(zz[p] - tq, 8192.f, -2.f);
        }
        __syncthreads();
    }

    // ---- drain the pending (final) iteration's screen: prv = acc1 ----
    {
        float* prv = acc1;
        bool hit = (fmaxf(prv[0], prv[1]) > At[0])
                 | (fmaxf(prv[2], prv[3]) > At[1])
                 | (fmaxf(prv[4], prv[5]) > At[2])
                 | (fmaxf(prv[6], prv[7]) > At[3]);
        if (hit) {
            #pragma unroll
            for (int p = 0; p < 4; p++) {
                #pragma unroll
                for (int h = 0; h < 2; h++) {
                    float d = __fmaf_rn(prv[2 * p + h], -0x1p-13f, zz[p]);
                    if (d < thr[p]) {
                        if (cnt[p] < CAP) cand[p][cnt[p]] = pnb + h;
                        cnt[p]++;
                        thr[p] = fminf(thr[p], d + M[p]);
                    }
                }
            }
        }
    }

    // ---- deferred exact rescoring of all recorded candidates ----
    const float* zbase = (const float*)(smem + ZS_OFF) + (mg * 32 + lq) * D_DIM;
    #pragma unroll
    for (int p = 0; p < 4; p++) {
        ull best = ~0ull;
        const float* zsp = zbase + p * 8 * D_DIM;
        if (__builtin_expect(cnt[p] <= CAP, 1)) {
            for (int i = 0; i < cnt[p]; i++)
                rescore(emb, zsp, zz[p], cand[p][i], best);
        } else {
            for (u32 n = 0; n < NEMB; n++)         // overflow: exact full-row scan
                rescore(emb, zsp, zz[p], n, best);
        }
        int rr = mg * 32 + lq + 8 * p;
        red[rr * 8 + nh * 4 + (lane & 3)] = best;
    }
    __syncthreads();

    if (tid < TL) {
        const ull* rr = red + tid * 8;
        ull mk = rr[0];
        #pragma unroll
        for (int x = 1; x < 8; x++) { ull v = rr[x]; if (v < mk) mk = v; }
        int idx = (int)(u32)(mk & 0xFFFFFFFFull);
        idx_s[tid] = idx;
        int ipos = LD_TOT + 1 + l0 + tid;
        if (ipos < out_size) out[ipos] = (float)idx;
    }
    __syncthreads();

    // ---- z_q_st = fl(z + fl(zq - z)) + loss (exact ref rounding) ----
    {
        int r = tid >> 1, h = tid & 1;
        int idx = idx_s[r];
        const float4* eq  = (const float4*)(emb + (size_t)idx * D_DIM + h * 32);
        const float4* zgl = (const float4*)(smem + ZS_OFF) + r * 16 + h * 8;
        int obase = (l0 + r) * D_DIM + h * 32;
        bool wr = (obase + 32) <= out_size;
        float4* og = (float4*)(out + obase);
        double ls = 0.0;
        #pragma unroll
        for (int q = 0; q < 8; q++) {
            float4 e4 = eq[q], z4 = zgl[q];
            float t0 = e4.x - z4.x, t1 = e4.y - z4.y, t2 = e4.z - z4.z, t3 = e4.w - z4.w;
            if (wr) {
                float4 o; o.x = z4.x + t0; o.y = z4.y + t1; o.z = z4.z + t2; o.w = z4.w + t3;
                og[q] = o;
            }
            ls += (double)t0 * t0 + (double)t1 * t1 + (double)t2 * t2 + (double)t3 * t3;
        }
        #pragma unroll
        for (int off = 16; off > 0; off >>= 1) ls += __shfl_down_sync(0xFFFFFFFFu, ls, off);
        if ((tid & 31) == 0) atomicAdd(&g_loss, ls);
    }

    // ---- fused finish: last block writes the loss scalar ----
    __syncthreads();
    if (tid == 0) {
        __threadfence();
        unsigned old = atomicAdd(&g_done, 1u);
        if (old == gridDim.x - 1) {
            double total = atomicAdd(&g_loss, 0.0);
            double mmean = total / (double)LD_TOT;
            if (LD_TOT < out_size) out[LD_TOT] = (float)(1.25 * mmean);
            g_done = 0u;                       // reset for next graph replay
        }
    }
}

extern "C" void kernel_launch(void* const* d_in, const int* in_sizes, int n_in,
                              void* d_out, int out_size)
{
    const float* zp = (const float*)d_in[0];
    const float* ep = (const float*)d_in[1];
    if (n_in >= 2 && in_sizes[0] == NEMB * D_DIM && in_sizes[1] == L_TOT * D_DIM) {
        const float* tmp = zp; zp = ep; ep = tmp;
    }
    float* out = (float*)d_out;

    cudaFuncSetAttribute(vq_main, cudaFuncAttributeMaxDynamicSharedMemorySize, SMEM_TOTAL);

    vq_prep<<<192, 256>>>(zp, ep);
    vq_main<<<L_TOT / TL, 256, SMEM_TOTAL>>>(zp, ep, out, out_size);
}